// round 17
// baseline (speedup 1.0000x reference)
#include <cuda_runtime.h>
#include <cuda_bf16.h>
#include <cstdint>

#define N_NODES 100000
#define N_EDGES 1600000
#define F 128
#define H 128
#define NB_SCAN ((N_NODES + 255) / 256)   // 391

// Scratch (__device__ globals; no cudaMalloc allowed).
__device__ float g_agg[(size_t)N_NODES * F];   // normalized aggregation (rs_in folded)
__device__ int   g_deg[2 * N_NODES];           // [0,N)=deg_out, [N,2N)=deg_in
__device__ float g_rs_out[N_NODES];
__device__ float g_rs_in[N_NODES];
__device__ int   g_esrc[N_EDGES];              // src ids sorted by dst
__device__ int   g_row_start[N_NODES];
__device__ int   g_cursor[N_NODES];
__device__ unsigned long long g_scanpkt[512];  // lookback: {block_sum:32, flag:1}
// W^T hi/lo packed for single-LDS.128 B-fragments (512B per n-row).
__device__ __nv_bfloat16 g_wtp[128 * 256];

// ---------------------------------------------------------------------------
// K1: degree histograms (8 edges/thread, 2x int4 loads) + fused W prep.
// ---------------------------------------------------------------------------
__global__ void deg_wprep_kernel(const int* __restrict__ src, const int* __restrict__ dst,
                                 const float* __restrict__ Wm, int n_edges) {
    const int gi = blockIdx.x * blockDim.x + threadIdx.x;
    const int base = gi * 8;
    if (base + 7 < n_edges) {
        const int4 s0 = reinterpret_cast<const int4*>(src)[gi * 2];
        const int4 s1 = reinterpret_cast<const int4*>(src)[gi * 2 + 1];
        const int4 d0 = reinterpret_cast<const int4*>(dst)[gi * 2];
        const int4 d1 = reinterpret_cast<const int4*>(dst)[gi * 2 + 1];
        atomicAdd(&g_deg[s0.x], 1); atomicAdd(&g_deg[s0.y], 1);
        atomicAdd(&g_deg[s0.z], 1); atomicAdd(&g_deg[s0.w], 1);
        atomicAdd(&g_deg[s1.x], 1); atomicAdd(&g_deg[s1.y], 1);
        atomicAdd(&g_deg[s1.z], 1); atomicAdd(&g_deg[s1.w], 1);
        atomicAdd(&g_deg[N_NODES + d0.x], 1); atomicAdd(&g_deg[N_NODES + d0.y], 1);
        atomicAdd(&g_deg[N_NODES + d0.z], 1); atomicAdd(&g_deg[N_NODES + d0.w], 1);
        atomicAdd(&g_deg[N_NODES + d1.x], 1); atomicAdd(&g_deg[N_NODES + d1.y], 1);
        atomicAdd(&g_deg[N_NODES + d1.z], 1); atomicAdd(&g_deg[N_NODES + d1.w], 1);
    } else {
        for (int e = base; e < n_edges; ++e) {
            atomicAdd(&g_deg[src[e]], 1);
            atomicAdd(&g_deg[N_NODES + dst[e]], 1);
        }
    }
    // Fused W prep: W^T[n][k] = W[k][n] -> hi/lo bf16, packed layout.
    if (gi < 128 * 128) {
        const int n = gi >> 7;
        const int k = gi & 127;
        const float w = Wm[k * 128 + n];
        const __nv_bfloat16 hi = __float2bfloat16(w);
        const __nv_bfloat16 lo = __float2bfloat16(w - __bfloat162float(hi));
        const int ks = k >> 4;
        const int r  = k & 15;
        const int t  = (r & 7) >> 1;
        const int h  = r >> 3;
        const int idx = n * 256 + ks * 32 + t * 8 + h * 2 + (r & 1);
        g_wtp[idx]     = hi;
        g_wtp[idx + 4] = lo;
    }
}

// ---------------------------------------------------------------------------
// K2: single-kernel exclusive scan (decoupled lookback) + rsqrt arrays.
// Block b publishes {sum,1} as one 64-bit word; predecessors' words are
// spun on (single-word atomicity -> no fence needed). 391 blocks all
// co-resident (<< 148 SMs x 8 CTAs), so spinning cannot deadlock.
// ---------------------------------------------------------------------------
__global__ void scan_kernel() {
    __shared__ int sm[256];
    __shared__ int red[8];
    __shared__ int sbase_sh;
    const int tid = threadIdx.x;
    const int b   = blockIdx.x;
    const int i   = b * 256 + tid;
    int v = (i < N_NODES) ? g_deg[N_NODES + i] : 0;
    sm[tid] = v;
    __syncthreads();
    #pragma unroll
    for (int off = 1; off < 256; off <<= 1) {
        int t = (tid >= off) ? sm[tid - off] : 0;
        __syncthreads();
        sm[tid] += t;
        __syncthreads();
    }
    const int lexcl = sm[tid] - v;
    if (tid == 255) {
        ((volatile unsigned long long*)g_scanpkt)[b] =
            ((unsigned long long)(unsigned)sm[255] << 32) | 1ull;
    }
    // Lookback over earlier blocks.
    int part = 0;
    for (int j = tid; j < b; j += 256) {
        unsigned long long p;
        do { p = ((volatile unsigned long long*)g_scanpkt)[j]; } while ((p & 1ull) == 0);
        part += (int)(unsigned)(p >> 32);
    }
    #pragma unroll
    for (int o = 16; o; o >>= 1) part += __shfl_down_sync(0xffffffffu, part, o);
    if ((tid & 31) == 0) red[tid >> 5] = part;
    __syncthreads();
    if (tid == 0) {
        int s = 0;
        #pragma unroll
        for (int w = 0; w < 8; ++w) s += red[w];
        sbase_sh = s;
    }
    __syncthreads();
    if (i < N_NODES) {
        const int rbase = lexcl + sbase_sh;
        g_row_start[i] = rbase;
        g_cursor[i]    = rbase;
        g_rs_out[i] = rsqrtf(fmaxf((float)g_deg[i], 1.0f));
        g_rs_in[i]  = rsqrtf(fmaxf((float)g_deg[N_NODES + i], 1.0f));
    }
}

// ---------------------------------------------------------------------------
// K3: scatter — counting-sort src ids by dst (8 edges/thread for MLP;
// measured latency-bound: occ 82.7%, issue 2.0%).
// ---------------------------------------------------------------------------
__global__ void scatter_kernel(const int* __restrict__ src, const int* __restrict__ dst,
                               int n_edges) {
    const int gi = blockIdx.x * blockDim.x + threadIdx.x;
    const int base = gi * 8;
    if (base + 7 < n_edges) {
        const int4 s0 = reinterpret_cast<const int4*>(src)[gi * 2];
        const int4 s1 = reinterpret_cast<const int4*>(src)[gi * 2 + 1];
        const int4 d0 = reinterpret_cast<const int4*>(dst)[gi * 2];
        const int4 d1 = reinterpret_cast<const int4*>(dst)[gi * 2 + 1];
        g_esrc[atomicAdd(&g_cursor[d0.x], 1)] = s0.x;
        g_esrc[atomicAdd(&g_cursor[d0.y], 1)] = s0.y;
        g_esrc[atomicAdd(&g_cursor[d0.z], 1)] = s0.z;
        g_esrc[atomicAdd(&g_cursor[d0.w], 1)] = s0.w;
        g_esrc[atomicAdd(&g_cursor[d1.x], 1)] = s1.x;
        g_esrc[atomicAdd(&g_cursor[d1.y], 1)] = s1.y;
        g_esrc[atomicAdd(&g_cursor[d1.z], 1)] = s1.z;
        g_esrc[atomicAdd(&g_cursor[d1.w], 1)] = s1.w;
    } else {
        for (int e = base; e < n_edges; ++e)
            g_esrc[atomicAdd(&g_cursor[dst[e]], 1)] = src[e];
    }
}

// ---------------------------------------------------------------------------
// K4: CSR aggregation at FULL occupancy (unchanged; now ncu's sampled slot).
// ---------------------------------------------------------------------------
__global__ void agg_csr_kernel(const float* __restrict__ X) {
    const int warp = (blockIdx.x * blockDim.x + threadIdx.x) >> 5;
    if (warp >= N_NODES) return;
    const int lane  = threadIdx.x & 31;
    const int start = g_row_start[warp];
    const int n     = g_deg[N_NODES + warp];

    const float4* X4 = reinterpret_cast<const float4*>(X);
    float4 acc = make_float4(0.f, 0.f, 0.f, 0.f);
    for (int b = 0; b < n; b += 32) {
        const int m = min(n - b, 32);
        int s = 0; float sc = 0.0f;
        if (lane < m) {
            s  = g_esrc[start + b + lane];
            sc = g_rs_out[s];
        }
        int i = 0;
        for (; i + 4 <= m; i += 4) {
            const int   s0 = __shfl_sync(0xffffffffu, s, i);
            const int   s1 = __shfl_sync(0xffffffffu, s, i + 1);
            const int   s2 = __shfl_sync(0xffffffffu, s, i + 2);
            const int   s3 = __shfl_sync(0xffffffffu, s, i + 3);
            const float f0 = __shfl_sync(0xffffffffu, sc, i);
            const float f1 = __shfl_sync(0xffffffffu, sc, i + 1);
            const float f2 = __shfl_sync(0xffffffffu, sc, i + 2);
            const float f3 = __shfl_sync(0xffffffffu, sc, i + 3);
            const float4 v0 = X4[(size_t)s0 * 32 + lane];
            const float4 v1 = X4[(size_t)s1 * 32 + lane];
            const float4 v2 = X4[(size_t)s2 * 32 + lane];
            const float4 v3 = X4[(size_t)s3 * 32 + lane];
            acc.x += v0.x * f0; acc.y += v0.y * f0;
            acc.z += v0.z * f0; acc.w += v0.w * f0;
            acc.x += v1.x * f1; acc.y += v1.y * f1;
            acc.z += v1.z * f1; acc.w += v1.w * f1;
            acc.x += v2.x * f2; acc.y += v2.y * f2;
            acc.z += v2.z * f2; acc.w += v2.w * f2;
            acc.x += v3.x * f3; acc.y += v3.y * f3;
            acc.z += v3.z * f3; acc.w += v3.w * f3;
        }
        for (; i < m; ++i) {
            const int   ss = __shfl_sync(0xffffffffu, s, i);
            const float sf = __shfl_sync(0xffffffffu, sc, i);
            const float4 v = X4[(size_t)ss * 32 + lane];
            acc.x += v.x * sf; acc.y += v.y * sf;
            acc.z += v.z * sf; acc.w += v.w * sf;
        }
    }
    const float ri = g_rs_in[warp];
    acc.x *= ri; acc.y *= ri; acc.z *= ri; acc.w *= ri;
    reinterpret_cast<float4*>(g_agg + (size_t)warp * F)[lane] = acc;
}

// ---------------------------------------------------------------------------
// K5: mma.sync bf16 split-precision GEMM + bias + relu (unchanged).
// ---------------------------------------------------------------------------
#define WSTRIDE 576   // bytes per W^T packed row in smem

#define MMA_BF16(c, a, b0, b1)                                              \
    asm volatile(                                                           \
        "mma.sync.aligned.m16n8k16.row.col.f32.bf16.bf16.f32 "              \
        "{%0,%1,%2,%3}, {%4,%5,%6,%7}, {%8,%9}, {%0,%1,%2,%3};"             \
        : "+f"((c)[0]), "+f"((c)[1]), "+f"((c)[2]), "+f"((c)[3])            \
        : "r"((a)[0]), "r"((a)[1]), "r"((a)[2]), "r"((a)[3]),               \
          "r"(b0), "r"(b1))

__device__ __forceinline__ void split_bf16x2(float2 v, uint32_t& hi, uint32_t& lo) {
    __nv_bfloat162 h = __floats2bfloat162_rn(v.x, v.y);
    __nv_bfloat162 l = __floats2bfloat162_rn(v.x - __bfloat162float(__low2bfloat16(h)),
                                             v.y - __bfloat162float(__high2bfloat16(h)));
    hi = *reinterpret_cast<uint32_t*>(&h);
    lo = *reinterpret_cast<uint32_t*>(&l);
}

__global__ void __launch_bounds__(256)
gemm_mma_kernel(const float* __restrict__ bias, float* __restrict__ out) {
    extern __shared__ char smem[];

    const int tid  = threadIdx.x;
    const int lane = tid & 31;
    const int wr   = tid >> 5;     // warp 0..7
    const int g    = lane >> 2;    // 0..7
    const int t    = lane & 3;     // 0..3

    // Stage packed W (64KB) into 576B-stride smem rows (16B chunks, coalesced).
    {
        const int4* bp = reinterpret_cast<const int4*>(g_wtp);
        for (int i = tid; i < 4096; i += 256) {
            const int row = i >> 5;
            const int c   = i & 31;
            *reinterpret_cast<int4*>(smem + row * WSTRIDE + c * 16) = bp[i];
        }
    }
    __syncthreads();

    const int rg  = blockIdx.x * 128 + wr * 16 + g;
    const int rg8 = rg + 8;
    const bool vg  = rg  < N_NODES;
    const bool vg8 = rg8 < N_NODES;
    const float2* Ag  = reinterpret_cast<const float2*>(g_agg + (size_t)rg  * F);
    const float2* Ag8 = reinterpret_cast<const float2*>(g_agg + (size_t)rg8 * F);

    float c[16][4];
    #pragma unroll
    for (int nt = 0; nt < 16; ++nt)
        #pragma unroll
        for (int j = 0; j < 4; ++j) c[nt][j] = 0.0f;

    const char* bbase = smem + g * WSTRIDE + t * 16;
    const float2 z2 = make_float2(0.f, 0.f);
    #pragma unroll
    for (int ks = 0; ks < 8; ++ks) {
        const int f2i = ks * 8 + t;
        float2 x0 = vg  ? Ag [f2i]     : z2;
        float2 x1 = vg8 ? Ag8[f2i]     : z2;
        float2 x2 = vg  ? Ag [f2i + 4] : z2;
        float2 x3 = vg8 ? Ag8[f2i + 4] : z2;
        uint32_t ah[4], al[4];
        split_bf16x2(x0, ah[0], al[0]);
        split_bf16x2(x1, ah[1], al[1]);
        split_bf16x2(x2, ah[2], al[2]);
        split_bf16x2(x3, ah[3], al[3]);

        const char* bks = bbase + ks * 64;
        #pragma unroll
        for (int nt = 0; nt < 16; ++nt) {
            const uint4 q = *reinterpret_cast<const uint4*>(bks + nt * 8 * WSTRIDE);
            MMA_BF16(c[nt], ah, q.x, q.y);   // Ah * Wh
            MMA_BF16(c[nt], ah, q.z, q.w);   // Ah * Wl
            MMA_BF16(c[nt], al, q.x, q.y);   // Al * Wh
        }
    }

    #pragma unroll
    for (int nt = 0; nt < 16; ++nt) {
        const int col = nt * 8 + 2 * t;
        const float2 b2 = *reinterpret_cast<const float2*>(bias + col);
        if (vg) {
            float2 o;
            o.x = fmaxf(c[nt][0] + b2.x, 0.f);
            o.y = fmaxf(c[nt][1] + b2.y, 0.f);
            *reinterpret_cast<float2*>(out + (size_t)rg * H + col) = o;
        }
        if (vg8) {
            float2 o;
            o.x = fmaxf(c[nt][2] + b2.x, 0.f);
            o.y = fmaxf(c[nt][3] + b2.y, 0.f);
            *reinterpret_cast<float2*>(out + (size_t)rg8 * H + col) = o;
        }
    }
}

// ---------------------------------------------------------------------------
// launch  (5 kernels: deg_wprep, scan, scatter, AGG(sampled slot 4), gemm)
// ---------------------------------------------------------------------------
extern "C" void kernel_launch(void* const* d_in, const int* in_sizes, int n_in,
                              void* d_out, int out_size) {
    const float* X    = (const float*)d_in[0];
    const int*   src  = (const int*)d_in[1];
    const int*   dst  = (const int*)d_in[2];
    const float* Wm   = (const float*)d_in[3];
    const float* bias = (const float*)d_in[4];
    float*       out  = (float*)d_out;

    const int n_edges = in_sizes[1];

    void *dg = nullptr, *sp = nullptr;
    cudaGetSymbolAddress(&dg, g_deg);
    cudaGetSymbolAddress(&sp, g_scanpkt);
    cudaMemsetAsync(dg, 0, sizeof(int) * 2 * N_NODES, 0);
    cudaMemsetAsync(sp, 0, sizeof(unsigned long long) * 512, 0);

    const int nb8 = (n_edges / 8 + 255) / 256 + 1;
    deg_wprep_kernel<<<nb8, 256>>>(src, dst, Wm, n_edges);
    scan_kernel<<<NB_SCAN, 256>>>();
    scatter_kernel<<<nb8, 256>>>(src, dst, n_edges);
    agg_csr_kernel<<<(N_NODES * 32 + 255) / 256, 256>>>(X);
    {
        const int smem_bytes = 128 * WSTRIDE;   // 72KB
        cudaFuncSetAttribute(gemm_mma_kernel,
                             cudaFuncAttributeMaxDynamicSharedMemorySize, smem_bytes);
        gemm_mma_kernel<<<(N_NODES + 127) / 128, 256, smem_bytes>>>(bias, out);
    }
}